// round 1
// baseline (speedup 1.0000x reference)
#include <cuda_runtime.h>
#include <cuda_bf16.h>
#include <stdint.h>

// Problem constants
#define T_SEQ   32768
#define IN_DIM  1024
#define H_DIM   20
#define NLAYER  4
#define G4      80          // 4*H
#define NSTEPS  (T_SEQ + NLAYER - 1)

// Scratch: layer-0 input projection (includes both biases). 32768*80*4B = 10.5 MB
__device__ float g_proj[T_SEQ * G4];

// ---------------------------------------------------------------------------
// Kernel 1: proj[t][g] = b_ih0[g] + b_hh0[g] + sum_k x[t][k] * W_ih0[g][k]
// Block handles 8 t-rows; 160 threads: g = tid%80, th = tid/80 picks row half.
// ---------------------------------------------------------------------------
__global__ __launch_bounds__(160) void proj_kernel(
    const float* __restrict__ x,
    const float* __restrict__ W,     // [80][1024]
    const float* __restrict__ bi,    // [80]
    const float* __restrict__ bh)    // [80]
{
    __shared__ __align__(16) float xs[8 * IN_DIM];
    const int t0 = blockIdx.x * 8;

    // coalesced stage of 8 x-rows (8*1024 floats = 2048 float4)
    const float4* xg  = (const float4*)(x + (size_t)t0 * IN_DIM);
    float4*       xs4 = (float4*)xs;
    for (int i = threadIdx.x; i < 8 * (IN_DIM / 4); i += blockDim.x)
        xs4[i] = xg[i];
    __syncthreads();

    const int tid = threadIdx.x;
    if (tid >= 160) return;
    const int g  = tid % 80;
    const int th = tid / 80;         // 0 or 1 -> rows [0..3] or [4..7]

    const float4* Wg = (const float4*)(W + (size_t)g * IN_DIM);
    float a0 = 0.f, a1 = 0.f, a2 = 0.f, a3 = 0.f;

    #pragma unroll 4
    for (int kk = 0; kk < IN_DIM / 4; ++kk) {
        float4 w4 = Wg[kk];
        float4 v0 = xs4[(th * 4 + 0) * (IN_DIM / 4) + kk];
        float4 v1 = xs4[(th * 4 + 1) * (IN_DIM / 4) + kk];
        float4 v2 = xs4[(th * 4 + 2) * (IN_DIM / 4) + kk];
        float4 v3 = xs4[(th * 4 + 3) * (IN_DIM / 4) + kk];
        a0 = fmaf(w4.x, v0.x, a0); a0 = fmaf(w4.y, v0.y, a0);
        a0 = fmaf(w4.z, v0.z, a0); a0 = fmaf(w4.w, v0.w, a0);
        a1 = fmaf(w4.x, v1.x, a1); a1 = fmaf(w4.y, v1.y, a1);
        a1 = fmaf(w4.z, v1.z, a1); a1 = fmaf(w4.w, v1.w, a1);
        a2 = fmaf(w4.x, v2.x, a2); a2 = fmaf(w4.y, v2.y, a2);
        a2 = fmaf(w4.z, v2.z, a2); a2 = fmaf(w4.w, v2.w, a2);
        a3 = fmaf(w4.x, v3.x, a3); a3 = fmaf(w4.y, v3.y, a3);
        a3 = fmaf(w4.z, v3.z, a3); a3 = fmaf(w4.w, v3.w, a3);
    }

    const float b = bi[g] + bh[g];
    const int tb = t0 + th * 4;
    g_proj[(size_t)(tb + 0) * G4 + g] = a0 + b;
    g_proj[(size_t)(tb + 1) * G4 + g] = a1 + b;
    g_proj[(size_t)(tb + 2) * G4 + g] = a2 + b;
    g_proj[(size_t)(tb + 3) * G4 + g] = a3 + b;
}

// ---------------------------------------------------------------------------
// Kernel 2: pipelined 4-layer LSTM recurrence. One block, warp l = layer l.
// ---------------------------------------------------------------------------
__device__ __forceinline__ unsigned long long fma2(
    unsigned long long a, unsigned long long b, unsigned long long c)
{
    unsigned long long d;
    asm("fma.rn.f32x2 %0, %1, %2, %3;" : "=l"(d) : "l"(a), "l"(b), "l"(c));
    return d;
}
__device__ __forceinline__ float lo32(unsigned long long u) {
    return __uint_as_float((unsigned)u);
}
__device__ __forceinline__ float hi32(unsigned long long u) {
    return __uint_as_float((unsigned)(u >> 32));
}
__device__ __forceinline__ float fast_sig(float x) {
    float e = __expf(-x);
    return __fdividef(1.f, 1.f + e);
}

__global__ __launch_bounds__(128, 1) void rnn_kernel(
    const float* __restrict__ W_hh0,   // [80][20]
    const float* __restrict__ W_ih_r,  // [3][80][20]
    const float* __restrict__ W_hh_r,  // [3][80][20]
    const float* __restrict__ b_ih_r,  // [3][80]
    const float* __restrict__ b_hh_r,  // [3][80]
    const float* __restrict__ lin_w,   // [20]
    const float* __restrict__ lin_b,   // [1]
    float* __restrict__ out)
{
    // h slot buffers: slot 0 = zeros (layer0's unused x), slot l+1 = layer l's h.
    // v for layer l = 40 contiguous floats starting at slot l.
    __shared__ __align__(16) float hbuf[2][5][H_DIM];
    __shared__ float actbuf[NLAYER][96];

    const int tid = threadIdx.x;
    const int l   = tid >> 5;     // layer == warp
    const int L   = tid & 31;     // lane

    for (int i = tid; i < 2 * 5 * H_DIM; i += blockDim.x)
        ((float*)hbuf)[i] = 0.f;

    // Per-lane weights: gates row = L + 32*s (rows >= 80 are zero dummies).
    // Columns 0..19 = W_ih (input = prev layer h), 20..39 = W_hh (own h).
    // Packed as f32x2 pairs: kk<10 -> x cols (2kk,2kk+1); kk>=10 -> h cols.
    unsigned long long wp[3][20];
    float bias[3];
    #pragma unroll
    for (int s3 = 0; s3 < 3; ++s3) {
        const int row = L + 32 * s3;
        const bool ok = (row < G4);
        float bsum = 0.f;
        if (ok && l > 0)
            bsum = b_ih_r[(l - 1) * G4 + row] + b_hh_r[(l - 1) * G4 + row];
        bias[s3] = bsum;
        #pragma unroll
        for (int kk = 0; kk < 20; ++kk) {
            float flo = 0.f, fhi = 0.f;
            if (ok) {
                if (kk < 10) {
                    if (l > 0) {
                        flo = W_ih_r[(l - 1) * 1600 + row * H_DIM + 2 * kk];
                        fhi = W_ih_r[(l - 1) * 1600 + row * H_DIM + 2 * kk + 1];
                    }
                } else {
                    const int k2 = 2 * (kk - 10);
                    if (l == 0) {
                        flo = W_hh0[row * H_DIM + k2];
                        fhi = W_hh0[row * H_DIM + k2 + 1];
                    } else {
                        flo = W_hh_r[(l - 1) * 1600 + row * H_DIM + k2];
                        fhi = W_hh_r[(l - 1) * 1600 + row * H_DIM + k2 + 1];
                    }
                }
            }
            wp[s3][kk] = (unsigned long long)__float_as_uint(flo) |
                         ((unsigned long long)__float_as_uint(fhi) << 32);
        }
    }
    const float lw = (L < H_DIM) ? lin_w[L] : 0.f;
    const float lb = lin_b[0];
    float c = 0.f;
    __syncthreads();

    for (int s = 0; s < NSTEPS; ++s) {
        const int t = s - l;
        const int p = s & 1;
        if (t >= 0 && t < T_SEQ) {
            // Gate pre-activations
            float pre0 = bias[0], pre1 = bias[1], pre2 = bias[2];
            if (l == 0) {
                pre0 = __ldg(&g_proj[(size_t)t * G4 + L]);
                pre1 = __ldg(&g_proj[(size_t)t * G4 + 32 + L]);
                pre2 = (L < 16) ? __ldg(&g_proj[(size_t)t * G4 + 64 + L]) : 0.f;
            }
            unsigned long long a0 = 0ull, a1 = 0ull, a2 = 0ull;
            const ulonglong2* vp = (const ulonglong2*)&hbuf[p][l][0];
            if (l == 0) {
                #pragma unroll
                for (int q = 5; q < 10; ++q) {   // only own-h part
                    ulonglong2 vv = vp[q];
                    a0 = fma2(wp[0][2*q], vv.x, a0); a0 = fma2(wp[0][2*q+1], vv.y, a0);
                    a1 = fma2(wp[1][2*q], vv.x, a1); a1 = fma2(wp[1][2*q+1], vv.y, a1);
                    a2 = fma2(wp[2][2*q], vv.x, a2); a2 = fma2(wp[2][2*q+1], vv.y, a2);
                }
            } else {
                #pragma unroll
                for (int q = 0; q < 10; ++q) {   // [x ; h]
                    ulonglong2 vv = vp[q];
                    a0 = fma2(wp[0][2*q], vv.x, a0); a0 = fma2(wp[0][2*q+1], vv.y, a0);
                    a1 = fma2(wp[1][2*q], vv.x, a1); a1 = fma2(wp[1][2*q+1], vv.y, a1);
                    a2 = fma2(wp[2][2*q], vv.x, a2); a2 = fma2(wp[2][2*q+1], vv.y, a2);
                }
            }
            float g0 = pre0 + lo32(a0) + hi32(a0);
            float g1 = pre1 + lo32(a1) + hi32(a1);
            float g2 = pre2 + lo32(a2) + hi32(a2);

            // Activations. Rows: 0..19 i(sig) 20..39 f(sig) 40..59 g(tanh) 60..79 o(sig)
            // slot0 rows 0..31 -> sig; slot1 rows 32..63 -> tanh iff 8<=L<28; slot2 -> sig
            const bool t1 = (L >= 8 && L < 28);
            float A0 = fast_sig(g0);
            float x1 = t1 ? 2.f * g1 : g1;
            float r1 = fast_sig(x1);
            float A1 = t1 ? 2.f * r1 - 1.f : r1;
            float A2 = fast_sig(g2);

            actbuf[l][L]      = A0;
            actbuf[l][32 + L] = A1;
            actbuf[l][64 + L] = A2;
            __syncwarp();

            float hnew = 0.f;
            if (L < H_DIM) {
                float ai = actbuf[l][L];
                float af = actbuf[l][20 + L];
                float ag = actbuf[l][40 + L];
                float ao = actbuf[l][60 + L];
                c = af * c + ai * ag;
                float e  = __expf(-2.f * c);
                float th = __fdividef(1.f - e, 1.f + e);
                hnew = ao * th;
                hbuf[p ^ 1][l + 1][L] = hnew;
            }
            if (l == 3 && t == T_SEQ - 1) {
                float part = hnew * lw;
                #pragma unroll
                for (int off = 16; off; off >>= 1)
                    part += __shfl_xor_sync(0xffffffffu, part, off);
                if (L == 0) out[0] = fast_sig(part + lb);
            }
        }
        __syncthreads();
    }
}

// ---------------------------------------------------------------------------
extern "C" void kernel_launch(void* const* d_in, const int* in_sizes, int n_in,
                              void* d_out, int out_size)
{
    const float* x      = (const float*)d_in[0];
    const float* W_ih0  = (const float*)d_in[1];
    const float* W_hh0  = (const float*)d_in[2];
    const float* b_ih0  = (const float*)d_in[3];
    const float* b_hh0  = (const float*)d_in[4];
    const float* W_ih_r = (const float*)d_in[5];
    const float* W_hh_r = (const float*)d_in[6];
    const float* b_ih_r = (const float*)d_in[7];
    const float* b_hh_r = (const float*)d_in[8];
    const float* lin_w  = (const float*)d_in[9];
    const float* lin_b  = (const float*)d_in[10];

    proj_kernel<<<T_SEQ / 8, 160>>>(x, W_ih0, b_ih0, b_hh0);
    rnn_kernel<<<1, 128>>>(W_hh0, W_ih_r, W_hh_r, b_ih_r, b_hh_r,
                           lin_w, lin_b, (float*)d_out);
}

// round 2
// speedup vs baseline: 1.2809x; 1.2809x over previous
#include <cuda_runtime.h>
#include <cuda_bf16.h>
#include <stdint.h>

// Problem constants
#define T_SEQ   32768
#define IN_DIM  1024
#define H_DIM   20
#define NLAYER  4
#define G4      80          // 4*H
#define NSTEPS  (T_SEQ + NLAYER - 1)

// Scratch: layer-0 input projection (includes both biases). 32768*80*4B = 10.5 MB
__device__ float g_proj[T_SEQ * G4];

// ---------------------------------------------------------------------------
// Kernel 1: proj[t][g] = b_ih0[g] + b_hh0[g] + sum_k x[t][k] * W_ih0[g][k]
// ---------------------------------------------------------------------------
__global__ __launch_bounds__(160) void proj_kernel(
    const float* __restrict__ x,
    const float* __restrict__ W,     // [80][1024]
    const float* __restrict__ bi,    // [80]
    const float* __restrict__ bh)    // [80]
{
    __shared__ __align__(16) float xs[8 * IN_DIM];
    const int t0 = blockIdx.x * 8;

    const float4* xg  = (const float4*)(x + (size_t)t0 * IN_DIM);
    float4*       xs4 = (float4*)xs;
    for (int i = threadIdx.x; i < 8 * (IN_DIM / 4); i += blockDim.x)
        xs4[i] = xg[i];
    __syncthreads();

    const int tid = threadIdx.x;
    if (tid >= 160) return;
    const int g  = tid % 80;
    const int th = tid / 80;

    const float4* Wg = (const float4*)(W + (size_t)g * IN_DIM);
    float a0 = 0.f, a1 = 0.f, a2 = 0.f, a3 = 0.f;

    #pragma unroll 4
    for (int kk = 0; kk < IN_DIM / 4; ++kk) {
        float4 w4 = Wg[kk];
        float4 v0 = xs4[(th * 4 + 0) * (IN_DIM / 4) + kk];
        float4 v1 = xs4[(th * 4 + 1) * (IN_DIM / 4) + kk];
        float4 v2 = xs4[(th * 4 + 2) * (IN_DIM / 4) + kk];
        float4 v3 = xs4[(th * 4 + 3) * (IN_DIM / 4) + kk];
        a0 = fmaf(w4.x, v0.x, a0); a0 = fmaf(w4.y, v0.y, a0);
        a0 = fmaf(w4.z, v0.z, a0); a0 = fmaf(w4.w, v0.w, a0);
        a1 = fmaf(w4.x, v1.x, a1); a1 = fmaf(w4.y, v1.y, a1);
        a1 = fmaf(w4.z, v1.z, a1); a1 = fmaf(w4.w, v1.w, a1);
        a2 = fmaf(w4.x, v2.x, a2); a2 = fmaf(w4.y, v2.y, a2);
        a2 = fmaf(w4.z, v2.z, a2); a2 = fmaf(w4.w, v2.w, a2);
        a3 = fmaf(w4.x, v3.x, a3); a3 = fmaf(w4.y, v3.y, a3);
        a3 = fmaf(w4.z, v3.z, a3); a3 = fmaf(w4.w, v3.w, a3);
    }

    const float b = bi[g] + bh[g];
    const int tb = t0 + th * 4;
    g_proj[(size_t)(tb + 0) * G4 + g] = a0 + b;
    g_proj[(size_t)(tb + 1) * G4 + g] = a1 + b;
    g_proj[(size_t)(tb + 2) * G4 + g] = a2 + b;
    g_proj[(size_t)(tb + 3) * G4 + g] = a3 + b;
}

// ---------------------------------------------------------------------------
// Kernel 2: pipelined 4-layer LSTM recurrence. One block, warp l = layer l.
// ---------------------------------------------------------------------------
__device__ __forceinline__ unsigned long long fma2(
    unsigned long long a, unsigned long long b, unsigned long long c)
{
    unsigned long long d;
    asm("fma.rn.f32x2 %0, %1, %2, %3;" : "=l"(d) : "l"(a), "l"(b), "l"(c));
    return d;
}
__device__ __forceinline__ float lo32(unsigned long long u) {
    return __uint_as_float((unsigned)u);
}
__device__ __forceinline__ float hi32(unsigned long long u) {
    return __uint_as_float((unsigned)(u >> 32));
}
__device__ __forceinline__ float tanh_fast(float x) {
    float y;
    asm("tanh.approx.f32 %0, %1;" : "=f"(y) : "f"(x));
    return y;
}
__device__ __forceinline__ float sig_fast(float x) {
    return fmaf(tanh_fast(0.5f * x), 0.5f, 0.5f);
}

__global__ __launch_bounds__(128, 1) void rnn_kernel(
    const float* __restrict__ W_hh0,   // [80][20]
    const float* __restrict__ W_ih_r,  // [3][80][20]
    const float* __restrict__ W_hh_r,  // [3][80][20]
    const float* __restrict__ b_ih_r,  // [3][80]
    const float* __restrict__ b_hh_r,  // [3][80]
    const float* __restrict__ lin_w,   // [20]
    const float* __restrict__ lin_b,   // [1]
    float* __restrict__ out)
{
    // h slot buffers: slot 0 = zeros (layer0's unused x), slot l+1 = layer l's h.
    __shared__ __align__(16) float hbuf[2][5][H_DIM];

    const int tid = threadIdx.x;
    const int l   = tid >> 5;     // layer == warp
    const int L   = tid & 31;     // lane

    for (int i = tid; i < 2 * 5 * H_DIM; i += blockDim.x)
        ((float*)hbuf)[i] = 0.f;

    // Per-lane weights: gate row = L + 32*s (rows >= 80 are zero dummies).
    // Columns 0..19 = W_ih (prev layer h), 20..39 = W_hh (own h). f32x2 packed.
    unsigned long long wp[3][20];
    float bias[3];
    #pragma unroll
    for (int s3 = 0; s3 < 3; ++s3) {
        const int row = L + 32 * s3;
        const bool ok = (row < G4);
        float bsum = 0.f;
        if (ok && l > 0)
            bsum = b_ih_r[(l - 1) * G4 + row] + b_hh_r[(l - 1) * G4 + row];
        bias[s3] = bsum;
        #pragma unroll
        for (int kk = 0; kk < 20; ++kk) {
            float flo = 0.f, fhi = 0.f;
            if (ok) {
                if (kk < 10) {
                    if (l > 0) {
                        flo = W_ih_r[(l - 1) * 1600 + row * H_DIM + 2 * kk];
                        fhi = W_ih_r[(l - 1) * 1600 + row * H_DIM + 2 * kk + 1];
                    }
                } else {
                    const int k2 = 2 * (kk - 10);
                    if (l == 0) {
                        flo = W_hh0[row * H_DIM + k2];
                        fhi = W_hh0[row * H_DIM + k2 + 1];
                    } else {
                        flo = W_hh_r[(l - 1) * 1600 + row * H_DIM + k2];
                        fhi = W_hh_r[(l - 1) * 1600 + row * H_DIM + k2 + 1];
                    }
                }
            }
            wp[s3][kk] = (unsigned long long)__float_as_uint(flo) |
                         ((unsigned long long)__float_as_uint(fhi) << 32);
        }
    }
    const float lw = (L < H_DIM) ? lin_w[L] : 0.f;
    const float lb = lin_b[0];
    float c = 0.f;

    // Distance-2 software pipeline for layer 0's g_proj reads.
    float pc0 = 0.f, pc1 = 0.f, pc2 = 0.f;   // for t
    float pn0 = 0.f, pn1 = 0.f, pn2 = 0.f;   // for t+1
    if (l == 0) {
        pc0 = __ldg(&g_proj[(size_t)0 * G4 + L]);
        pc1 = __ldg(&g_proj[(size_t)0 * G4 + 32 + L]);
        pc2 = (L < 16) ? __ldg(&g_proj[(size_t)0 * G4 + 64 + L]) : 0.f;
        pn0 = __ldg(&g_proj[(size_t)1 * G4 + L]);
        pn1 = __ldg(&g_proj[(size_t)1 * G4 + 32 + L]);
        pn2 = (L < 16) ? __ldg(&g_proj[(size_t)1 * G4 + 64 + L]) : 0.f;
    }
    __syncthreads();

    const unsigned FULL = 0xffffffffu;

    for (int s = 0; s < NSTEPS; ++s) {
        const int t = s - l;
        const int p = s & 1;
        if (t >= 0 && t < T_SEQ) {
            float pre0 = bias[0], pre1 = bias[1], pre2 = bias[2];
            if (l == 0) {
                pre0 = pc0; pre1 = pc1; pre2 = pc2;
                pc0 = pn0; pc1 = pn1; pc2 = pn2;
                const int tp = t + 2;
                if (tp < T_SEQ) {
                    pn0 = __ldg(&g_proj[(size_t)tp * G4 + L]);
                    pn1 = __ldg(&g_proj[(size_t)tp * G4 + 32 + L]);
                    pn2 = (L < 16) ? __ldg(&g_proj[(size_t)tp * G4 + 64 + L]) : 0.f;
                }
            }
            unsigned long long a0 = 0ull, a1 = 0ull, a2 = 0ull;
            const ulonglong2* vp = (const ulonglong2*)&hbuf[p][l][0];
            if (l == 0) {
                #pragma unroll
                for (int q = 5; q < 10; ++q) {   // only own-h part
                    ulonglong2 vv = vp[q];
                    a0 = fma2(wp[0][2*q], vv.x, a0); a0 = fma2(wp[0][2*q+1], vv.y, a0);
                    a1 = fma2(wp[1][2*q], vv.x, a1); a1 = fma2(wp[1][2*q+1], vv.y, a1);
                    a2 = fma2(wp[2][2*q], vv.x, a2); a2 = fma2(wp[2][2*q+1], vv.y, a2);
                }
            } else {
                #pragma unroll
                for (int q = 0; q < 10; ++q) {   // [x ; h]
                    ulonglong2 vv = vp[q];
                    a0 = fma2(wp[0][2*q], vv.x, a0); a0 = fma2(wp[0][2*q+1], vv.y, a0);
                    a1 = fma2(wp[1][2*q], vv.x, a1); a1 = fma2(wp[1][2*q+1], vv.y, a1);
                    a2 = fma2(wp[2][2*q], vv.x, a2); a2 = fma2(wp[2][2*q+1], vv.y, a2);
                }
            }
            float g0 = pre0 + lo32(a0) + hi32(a0);
            float g1 = pre1 + lo32(a1) + hi32(a1);
            float g2 = pre2 + lo32(a2) + hi32(a2);

            // Activations. Rows: 0..19 i(sig) 20..39 f(sig) 40..59 g(tanh) 60..79 o(sig)
            // g0 rows 0..31 -> sig; g1 rows 32..63 -> tanh iff lane in [8,28); g2 -> sig
            const bool t1 = (L >= 8 && L < 28);
            float A0 = sig_fast(g0);
            float x1 = t1 ? g1 : 0.5f * g1;
            float r1 = tanh_fast(x1);
            float A1 = t1 ? r1 : fmaf(r1, 0.5f, 0.5f);
            float A2 = sig_fast(g2);

            // Shuffle transpose: lane L (<20) gathers its i,f,g,o.
            //   i: row L        -> own A0
            //   f: row 20+L     -> L<12: A0 lane 20+L ; else A1 lane L-12
            //   g: row 40+L     -> A1 lane 8+L
            //   o: row 60+L     -> L<4: A1 lane 28+L ; else A2 lane L-4
            float ai  = A0;
            float afa = __shfl_sync(FULL, A0, (20 + L) & 31);
            float afb = __shfl_sync(FULL, A1, (L - 12) & 31);
            float ag  = __shfl_sync(FULL, A1, (8 + L) & 31);
            float aoa = __shfl_sync(FULL, A1, (28 + L) & 31);
            float aob = __shfl_sync(FULL, A2, (L - 4) & 31);
            float af  = (L < 12) ? afa : afb;
            float ao  = (L < 4)  ? aoa : aob;

            float hnew = 0.f;
            if (L < H_DIM) {
                c = fmaf(af, c, ai * ag);
                hnew = ao * tanh_fast(c);
                hbuf[p ^ 1][l + 1][L] = hnew;
            }
            if (l == 3 && t == T_SEQ - 1) {
                float part = hnew * lw;
                #pragma unroll
                for (int off = 16; off; off >>= 1)
                    part += __shfl_xor_sync(FULL, part, off);
                if (L == 0) out[0] = sig_fast(part + lb);
            }
        }
        __syncthreads();
    }
}

// ---------------------------------------------------------------------------
extern "C" void kernel_launch(void* const* d_in, const int* in_sizes, int n_in,
                              void* d_out, int out_size)
{
    const float* x      = (const float*)d_in[0];
    const float* W_ih0  = (const float*)d_in[1];
    const float* W_hh0  = (const float*)d_in[2];
    const float* b_ih0  = (const float*)d_in[3];
    const float* b_hh0  = (const float*)d_in[4];
    const float* W_ih_r = (const float*)d_in[5];
    const float* W_hh_r = (const float*)d_in[6];
    const float* b_ih_r = (const float*)d_in[7];
    const float* b_hh_r = (const float*)d_in[8];
    const float* lin_w  = (const float*)d_in[9];
    const float* lin_b  = (const float*)d_in[10];

    proj_kernel<<<T_SEQ / 8, 160>>>(x, W_ih0, b_ih0, b_hh0);
    rnn_kernel<<<1, 128>>>(W_hh0, W_ih_r, W_hh_r, b_ih_r, b_hh_r,
                           lin_w, lin_b, (float*)d_out);
}